// round 15
// baseline (speedup 1.0000x reference)
#include <cuda_runtime.h>
#include <cuda_fp16.h>
#include <cstdint>
#include <cstddef>

// SubnetGate hard-routed MoE MLP, sm_103 harness (no tcgen05 under compute_103).
//   out[t] = relu(x[t] @ W1[e] + b1[e]) @ W2[e] + b2[e],  e = groups[t]
// B=8192, D_IN=512, D_H=2048, D_OUT=512, E=8, fp32 I/O (groups int32, probed).
//
// R15: shrink the exposed pre-GEMM window.
//  - Router parallelized: count(32 blocks) -> prefix(1 block) -> scatter(32
//    blocks, global atomics). Perm order is nondeterministic but each token's
//    output is computed independently from its own row -> bit-identical out.
//  - prep_w1 split into two N-halves; GEMM1 split into two y-halves so the
//    first half starts as soon as chunk A + x-convert land.

namespace {
constexpr int B_TOK  = 8192;
constexpr int D_IN   = 512;
constexpr int D_H    = 2048;
constexpr int D_OUT  = 512;
constexpr int NE     = 8;
constexpr int TM     = 128;
constexpr int NT_MAX = 72;            // sum ceil(c_e/128) <= 64+7
constexpr int ROWS   = NT_MAX * TM;   // 9216
constexpr int BK     = 64;            // halves per k-tile (128B rows)
constexpr int BN     = 128;
constexpr int ST     = 72;            // smem row stride in halves (conflict-free frag loads)
constexpr int AS_SZ  = TM * ST;       // halves per stage
constexpr int BS_SZ  = BN * ST;
constexpr int SMEM_BYTES = 2 * (AS_SZ + BS_SZ) * 2;   // 73728 B
constexpr int RB     = 32;            // router blocks
}

__device__ int g_perm[ROWS];            // sorted pos -> token (-1 = pad)
__device__ int g_tile_expert[NT_MAX];   // tile -> expert (-1 inactive)
__device__ int g_blkcnt[RB][NE];        // per-block expert counts
__device__ int g_cur[NE];               // scatter cursors (reset by prefix)
__device__ __align__(16) __half g_a1[(size_t)B_TOK * D_IN];       // x as half, TOKEN order
__device__ __align__(16) __half g_w1t[(size_t)NE * D_H * D_IN];   // W1^T [e][n][k] half
__device__ __align__(16) __half g_w2t[(size_t)NE * D_OUT * D_H];  // W2^T [e][n][k] half
__device__ __align__(16) __half g_h[(size_t)ROWS * D_H];          // hidden (half, sorted)

__device__ __forceinline__ uint32_t h2_as_u32(__half2 h) {
    return *reinterpret_cast<uint32_t*>(&h);
}

__device__ __forceinline__ void cp_async16(void* smem_dst, const void* gsrc) {
    uint32_t s = (uint32_t)__cvta_generic_to_shared(smem_dst);
    asm volatile("cp.async.cg.shared.global [%0], [%1], 16;\n" :: "r"(s), "l"(gsrc));
}
// Predicated variant: pred=false => src-size 0 => zero-fill 16B.
__device__ __forceinline__ void cp_async16_z(void* smem_dst, const void* gsrc, bool pred) {
    uint32_t s = (uint32_t)__cvta_generic_to_shared(smem_dst);
    int sz = pred ? 16 : 0;
    asm volatile("cp.async.cg.shared.global [%0], [%1], 16, %2;\n"
                 :: "r"(s), "l"(gsrc), "r"(sz));
}

// Probe groups dtype from the first 512 ints (valid under both layouts):
// int64 data (values 0..7, LE) => all odd int32 words zero.
__device__ __forceinline__ bool probe_is_i32(const int* g32, int tid, int* sh_or) {
    if (tid == 0) *sh_or = 0;
    __syncthreads();
    int v = g32[2 * tid + 1];     // tid < 256 -> indices 1..511
    if (v) atomicOr(sh_or, 1);
    __syncthreads();
    return *sh_or != 0;
}

// ---------------------------------------------------------------------------
// Router stage 1: per-block expert counts + g_perm init. grid RB x 256.
// ---------------------------------------------------------------------------
__global__ void route_count(const int* __restrict__ g32) {
    __shared__ int cnt[NE];
    __shared__ int sh_or;
    const int tid = threadIdx.x;
    if (tid < NE) cnt[tid] = 0;
    const bool is_i32 = probe_is_i32(g32, tid, &sh_or);   // includes syncs

    const int t = blockIdx.x * 256 + tid;
    const int e = (is_i32 ? g32[t] : g32[2 * t]) & (NE - 1);
    atomicAdd(&cnt[e], 1);

    // init perm slice: ROWS = RB * 288
    for (int i = tid; i < 288; i += 256) g_perm[blockIdx.x * 288 + i] = -1;

    __syncthreads();
    if (tid < NE) g_blkcnt[blockIdx.x][tid] = cnt[tid];
}

// ---------------------------------------------------------------------------
// Router stage 2: bases, cursors, tile->expert map. 1 block, 128 threads.
// ---------------------------------------------------------------------------
__global__ void route_prefix() {
    __shared__ int base[NE + 1];
    if (threadIdx.x == 0) {
        int b = 0;
        for (int e = 0; e < NE; e++) {
            int c = 0;
            for (int blk = 0; blk < RB; blk++) c += g_blkcnt[blk][e];
            base[e] = b;
            g_cur[e] = b;
            b += ((c + TM - 1) / TM) * TM;
        }
        base[NE] = b;
    }
    __syncthreads();
    for (int t = threadIdx.x; t < NT_MAX; t += blockDim.x) {
        int row0 = t * TM;
        int e = -1;
        if (row0 < base[NE])
            for (int k = 0; k < NE; k++)
                if (row0 >= base[k] && row0 < base[k + 1]) e = k;
        g_tile_expert[t] = e;
    }
}

// ---------------------------------------------------------------------------
// Router stage 3: scatter tokens via global cursors. grid RB x 256.
// ---------------------------------------------------------------------------
__global__ void route_scatter(const int* __restrict__ g32) {
    __shared__ int sh_or;
    const int tid = threadIdx.x;
    const bool is_i32 = probe_is_i32(g32, tid, &sh_or);

    const int t = blockIdx.x * 256 + tid;
    const int e = (is_i32 ? g32[t] : g32[2 * t]) & (NE - 1);
    int pos = atomicAdd(&g_cur[e], 1);
    g_perm[pos] = t;
}

// ---------------------------------------------------------------------------
// Convert x -> half in TOKEN order (no routing dependency; coalesced).
// ---------------------------------------------------------------------------
__global__ void convert_x_kernel(const float* __restrict__ x) {
    const size_t base = ((size_t)blockIdx.x * 256 + threadIdx.x) * 8;
    float4 a = *(const float4*)(x + base);
    float4 b = *(const float4*)(x + base + 4);
    uint4 o;
    o.x = h2_as_u32(__floats2half2_rn(a.x, a.y));
    o.y = h2_as_u32(__floats2half2_rn(a.z, a.w));
    o.z = h2_as_u32(__floats2half2_rn(b.x, b.y));
    o.w = h2_as_u32(__floats2half2_rn(b.z, b.w));
    *(uint4*)(g_a1 + base) = o;
}

// ---------------------------------------------------------------------------
// Prep: transpose W [e][K][N] -> W^T [e][N][K], converted to half.
// 32x32 fp32 smem tiles; grid (nBlocks, K/32, E); bn0 = N-chunk offset.
// ---------------------------------------------------------------------------
template <int K, int N, bool W2SEL>
__global__ void prep_w_kernel(const float* __restrict__ src, int bn0) {
    __shared__ float s[32][33];
    __half* dst = W2SEL ? g_w2t : g_w1t;
    const int tid = threadIdx.x;
    const int bn = blockIdx.x + bn0, bk = blockIdx.y, e = blockIdx.z;
    const int r  = tid >> 3;
    const int c4 = (tid & 7) * 4;

    float4 v = *(const float4*)(src + ((size_t)e * K + 32 * bk + r) * N + 32 * bn + c4);
    s[r][c4 + 0] = v.x; s[r][c4 + 1] = v.y; s[r][c4 + 2] = v.z; s[r][c4 + 3] = v.w;
    __syncthreads();

    uint2 o;
    o.x = h2_as_u32(__floats2half2_rn(s[c4 + 0][r], s[c4 + 1][r]));
    o.y = h2_as_u32(__floats2half2_rn(s[c4 + 2][r], s[c4 + 3][r]));
    *(uint2*)(dst + ((size_t)e * N + 32 * bn + r) * K + 32 * bk + c4) = o;
}

// ---------------------------------------------------------------------------
// Grouped GEMM: C = op(A @ W^T[e] + bias[e])
// 128x128 block tile, BK=64, 8 warps (2x4), 64x32 warp tile, fp16 m16n8k16,
// fp32 accumulate, cp.async double-buffer. y0 = N-tile offset (GEMM1 halves).
//   LAYER1: A = g_a1 gathered via g_perm (zero-fill pads), relu, -> g_h sorted
//  !LAYER1: A = g_h contiguous, -> scatter fp32 to out via g_perm
// ---------------------------------------------------------------------------
template <int K, int NTOT, bool LAYER1>
__global__ __launch_bounds__(256, 2)
void gemm_kernel(const float* __restrict__ bias, float* __restrict__ Oout, int y0) {
    extern __shared__ __half smem[];
    __half* AsBase = smem;                    // 2 stages TM x BK (stride ST)
    __half* BsBase = smem + 2 * AS_SZ;        // 2 stages BN x BK (stride ST)

    const int tile = blockIdx.x;
    const int e = g_tile_expert[tile];
    if (e < 0) return;

    const __half* Wt = LAYER1 ? g_w1t : g_w2t;

    const int n0 = (blockIdx.y + y0) * BN;
    const __half* Brow0 = Wt + ((size_t)e * NTOT + n0) * K;
    const float*  bp    = bias + (size_t)e * NTOT + n0;

    const int tid  = threadIdx.x;
    const int lane = tid & 31;
    const int warp = tid >> 5;
    const int wm   = warp >> 2;  // 0..1
    const int wn   = warp & 3;   // 0..3

    // A row sources. LAYER1: gather via perm (4 rows per thread, pads -> null).
    const __half* arow[4];
#pragma unroll
    for (int j = 0; j < 4; j++) {
        int r = (tid >> 3) + 32 * j;
        if (LAYER1) {
            int tok = g_perm[tile * TM + r];
            arow[j] = (tok >= 0) ? (g_a1 + (size_t)tok * K) : nullptr;
        } else {
            arow[j] = g_h + ((size_t)tile * TM + r) * K;
        }
    }

    float acc[4][4][4];
#pragma unroll
    for (int i = 0; i < 4; i++)
#pragma unroll
        for (int j = 0; j < 4; j++)
#pragma unroll
            for (int q = 0; q < 4; q++) acc[i][j][q] = 0.f;

    const int aco = (tid & 7) * 8;   // A: 16B chunk col offset within BK

    // Stage 128 rows x 64 halves for A (per-row pointers) and B (contiguous).
    auto stage = [&](int k0, int buf) {
        __half* as = AsBase + buf * AS_SZ;
        __half* bs = BsBase + buf * BS_SZ;
#pragma unroll
        for (int j = 0; j < 4; j++) {
            int r = (tid >> 3) + 32 * j;
            const __half* src = arow[j] ? (arow[j] + k0 + aco) : g_a1;
            cp_async16_z(&as[r * ST + aco], src, arow[j] != nullptr);
        }
#pragma unroll
        for (int j = 0; j < 4; j++) {
            int c = tid + 256 * j;
            int r = c >> 3;
            int co = (c & 7) * 8;
            cp_async16(&bs[r * ST + co], Brow0 + (size_t)r * K + k0 + co);
        }
    };

    constexpr int NIT = K / BK;

    stage(0, 0);
    asm volatile("cp.async.commit_group;\n");

    for (int it = 0; it < NIT; it++) {
        const int buf = it & 1;
        if (it + 1 < NIT) {
            stage((it + 1) * BK, buf ^ 1);
            asm volatile("cp.async.commit_group;\n");
            asm volatile("cp.async.wait_group 1;\n");
        } else {
            asm volatile("cp.async.wait_group 0;\n");
        }
        __syncthreads();

        const __half* As = AsBase + buf * AS_SZ;
        const __half* Bs = BsBase + buf * BS_SZ;

#pragma unroll
        for (int ks = 0; ks < BK / 16; ks++) {
            const int kq = ks * 16 + (lane & 3) * 2;
            uint32_t af[4][4], bf[4][2];
#pragma unroll
            for (int mf = 0; mf < 4; mf++) {
                int m = wm * 64 + mf * 16 + (lane >> 2);
                // m16n8k16 f16 A frag: a0=(m,k:k+1) a1=(m+8,k:k+1) a2=(m,k+8:k+9) a3=(m+8,k+8:k+9)
                af[mf][0] = *(const uint32_t*)&As[m * ST + kq];
                af[mf][1] = *(const uint32_t*)&As[(m + 8) * ST + kq];
                af[mf][2] = *(const uint32_t*)&As[m * ST + kq + 8];
                af[mf][3] = *(const uint32_t*)&As[(m + 8) * ST + kq + 8];
            }
#pragma unroll
            for (int nf = 0; nf < 4; nf++) {
                int n = wn * 32 + nf * 8 + (lane >> 2);
                // B frag (col): b0=(k:k+1, n), b1=(k+8:k+9, n); Bs rows n-major, k contiguous
                bf[nf][0] = *(const uint32_t*)&Bs[n * ST + kq];
                bf[nf][1] = *(const uint32_t*)&Bs[n * ST + kq + 8];
            }
#pragma unroll
            for (int mf = 0; mf < 4; mf++)
#pragma unroll
                for (int nf = 0; nf < 4; nf++) {
                    asm volatile(
                        "mma.sync.aligned.m16n8k16.row.col.f32.f16.f16.f32 "
                        "{%0,%1,%2,%3}, {%4,%5,%6,%7}, {%8,%9}, {%0,%1,%2,%3};\n"
                        : "+f"(acc[mf][nf][0]), "+f"(acc[mf][nf][1]),
                          "+f"(acc[mf][nf][2]), "+f"(acc[mf][nf][3])
                        : "r"(af[mf][0]), "r"(af[mf][1]),
                          "r"(af[mf][2]), "r"(af[mf][3]),
                          "r"(bf[nf][0]), "r"(bf[nf][1]));
                }
        }
        __syncthreads();
    }

    // Epilogue: bias (+relu); layer1 -> half g_h (sorted), layer2 -> scatter fp32.
#pragma unroll
    for (int mf = 0; mf < 4; mf++) {
#pragma unroll
        for (int half_i = 0; half_i < 2; half_i++) {
            int r = wm * 64 + mf * 16 + (lane >> 2) + half_i * 8;
            float* orow_f = nullptr;
            __half* orow_h = nullptr;
            if (!LAYER1) {
                int tok = g_perm[tile * TM + r];
                if (tok >= 0) orow_f = Oout + (size_t)tok * NTOT + n0;
            } else {
                orow_h = g_h + ((size_t)tile * TM + r) * NTOT + n0;
            }
#pragma unroll
            for (int nf = 0; nf < 4; nf++) {
                int c = wn * 32 + nf * 8 + 2 * (lane & 3);
                float v0 = acc[mf][nf][half_i * 2 + 0] + bp[c];
                float v1 = acc[mf][nf][half_i * 2 + 1] + bp[c + 1];
                if (LAYER1) { v0 = fmaxf(v0, 0.f); v1 = fmaxf(v1, 0.f); }
                if (!LAYER1) {
                    if (orow_f) { orow_f[c] = v0; orow_f[c + 1] = v1; }
                } else {
                    *(uint32_t*)&orow_h[c] = h2_as_u32(__floats2half2_rn(v0, v1));
                }
            }
        }
    }
}

extern "C" void kernel_launch(void* const* d_in, const int* in_sizes, int n_in,
                              void* d_out, int out_size) {
    const float* x      = (const float*)d_in[0];
    const int*   groups = (const int*)d_in[1];
    const float* W1     = (const float*)d_in[2];
    const float* b1     = (const float*)d_in[3];
    const float* W2     = (const float*)d_in[4];
    const float* b2     = (const float*)d_in[5];
    float*       out    = (float*)d_out;

    // One-time side streams + events for capture-legal fork/join.
    static cudaStream_t s2 = nullptr, s3 = nullptr;
    static cudaEvent_t evFork = nullptr, evW1a = nullptr, evW1b = nullptr,
                       evW2 = nullptr, evX = nullptr, evRoute = nullptr,
                       evG1b = nullptr;
    if (!s2) {
        cudaStreamCreateWithFlags(&s2, cudaStreamNonBlocking);
        cudaStreamCreateWithFlags(&s3, cudaStreamNonBlocking);
        cudaEventCreateWithFlags(&evFork,  cudaEventDisableTiming);
        cudaEventCreateWithFlags(&evW1a,   cudaEventDisableTiming);
        cudaEventCreateWithFlags(&evW1b,   cudaEventDisableTiming);
        cudaEventCreateWithFlags(&evW2,    cudaEventDisableTiming);
        cudaEventCreateWithFlags(&evX,     cudaEventDisableTiming);
        cudaEventCreateWithFlags(&evRoute, cudaEventDisableTiming);
        cudaEventCreateWithFlags(&evG1b,   cudaEventDisableTiming);
    }

    cudaFuncSetAttribute(gemm_kernel<D_IN, D_H, true>,
                         cudaFuncAttributeMaxDynamicSharedMemorySize, SMEM_BYTES);
    cudaFuncSetAttribute(gemm_kernel<D_H, D_OUT, false>,
                         cudaFuncAttributeMaxDynamicSharedMemorySize, SMEM_BYTES);

    // Fork: W1^T chunks on s2, x convert on s3.
    cudaEventRecord(evFork, 0);
    cudaStreamWaitEvent(s2, evFork, 0);
    cudaStreamWaitEvent(s3, evFork, 0);
    prep_w_kernel<D_IN, D_H, false>
        <<<dim3(32, D_IN / 32, NE), 256, 0, s2>>>(W1, 0);    // n in [0,1024)
    cudaEventRecord(evW1a, s2);
    prep_w_kernel<D_IN, D_H, false>
        <<<dim3(32, D_IN / 32, NE), 256, 0, s2>>>(W1, 32);   // n in [1024,2048)
    cudaEventRecord(evW1b, s2);
    convert_x_kernel<<<(B_TOK * D_IN) / (256 * 8), 256, 0, s3>>>(x);
    cudaEventRecord(evX, s3);

    // Main stream: parallel router.
    route_count<<<RB, 256>>>(groups);
    route_prefix<<<1, 128>>>();
    route_scatter<<<RB, 256>>>(groups);
    cudaEventRecord(evRoute, 0);

    // Deferred: W2^T overlaps GEMM1 (DRAM headroom there).
    cudaStreamWaitEvent(s2, evRoute, 0);
    prep_w_kernel<D_H, D_OUT, true>
        <<<dim3(D_OUT / 32, D_H / 32, NE), 256, 0, s2>>>(W2, 0);
    cudaEventRecord(evW2, s2);

    // GEMM1 half A on main stream (route in-order; needs W1 chunk A + x_half).
    cudaStreamWaitEvent(0, evW1a, 0);
    cudaStreamWaitEvent(0, evX, 0);
    gemm_kernel<D_IN, D_H, true>
        <<<dim3(NT_MAX, D_H / BN / 2), 256, SMEM_BYTES>>>(b1, nullptr, 0);

    // GEMM1 half B on s3 (convert_x in-order there; needs route + W1 chunk B).
    cudaStreamWaitEvent(s3, evRoute, 0);
    cudaStreamWaitEvent(s3, evW1b, 0);
    gemm_kernel<D_IN, D_H, true>
        <<<dim3(NT_MAX, D_H / BN / 2), 256, SMEM_BYTES, s3>>>(b1, nullptr, D_H / BN / 2);
    cudaEventRecord(evG1b, s3);

    // GEMM2 after both GEMM1 halves + W2^T.
    cudaStreamWaitEvent(0, evG1b, 0);
    cudaStreamWaitEvent(0, evW2, 0);
    gemm_kernel<D_H, D_OUT, false>
        <<<dim3(NT_MAX, D_OUT / BN), 256, SMEM_BYTES>>>(b2, out, 0);
}